// round 13
// baseline (speedup 1.0000x reference)
#include <cuda_runtime.h>
#include <math.h>

// Problem constants (hardcoded in reference)
#define B 32
#define D 128
#define K 512
#define C 10
#define NT 1024
#define NFLAG 32          // one flag per CTA's fac2 k-slice

// Cross-CTA state
__device__ float g_fac2[C][K];
__device__ __align__(16) int g_pflag[NFLAG];
__device__ int g_done = 0;

__device__ __forceinline__ void st_release_gpu(int* p, int v) {
    asm volatile("st.release.gpu.global.s32 [%0], %1;" :: "l"(p), "r"(v) : "memory");
}
__device__ __forceinline__ int4 ld_volatile_v4(const int4* p) {
    int4 v;
    asm volatile("ld.volatile.global.v4.s32 {%0,%1,%2,%3}, [%4];"
                 : "=r"(v.x), "=r"(v.y), "=r"(v.z), "=r"(v.w) : "l"(p) : "memory");
    return v;
}
__device__ __forceinline__ void fence_acq_rel_gpu() {
    asm volatile("fence.acq_rel.gpu;" ::: "memory");
}
__device__ __forceinline__ void bar_sync_grp(int id, int count) {
    asm volatile("bar.sync %0, %1;" :: "r"(id), "r"(count) : "memory");
}

// 32 symmetric CTAs x 1024 threads. CTA b:
//   threads 640..1023: compute fac2[:, 16b..16b+16) (8 KB of V), publish+flag,
//                      then join phase B late (hidden under the L1 wf queue).
//   threads 0..639   : phase B immediately (fac1 row b, d-groups 0..4).
//   Then: poll 32 flags (already set), fold, warp-per-class dot, fast softmax.
__global__ __launch_bounds__(NT, 1) void fused_kernel(
    const float* __restrict__ x,
    const float* __restrict__ mu,
    const float* __restrict__ U,
    const float* __restrict__ V,
    float* __restrict__ out) {
    __shared__ float sx[D];
    __shared__ float smu[C * D];            // all of mu (5 KB)
    __shared__ float part[8][K];            // fac1 d-group partials (16 KB)
    __shared__ float4 part2[C][4][8];       // fac2-slice d-split partials (5 KB)
    __shared__ float f1s[K];
    __shared__ float hrow[C];

    const int t    = threadIdx.x;
    const int w    = t >> 5;
    const int lane = t & 31;
    const int g    = t >> 7;                // d-group 0..7
    const int tt   = t & 127;               // float4 col, full K
    const int row  = blockIdx.x;
    const int bx4  = row * 4;               // slice start in float4 units

    // stage sx and mu into smem
    if (t < D) sx[t] = x[row * D + t];
    smu[t] = mu[t];
    if (t < C * D - NT) smu[NT + t] = mu[NT + t];

    const float*  Ug = U + g * 16 * K;
    const float4* V4 = reinterpret_cast<const float4*>(V);

    float4 wv[8];
    float4 av[8];
    const int idx = t - 640;                // phase-A index (valid when t>=640)
    int ac = 0, aq = 0, ads = 0;
    if (t < 640) {
        // group B: front-batch phase-B load batch 1
#pragma unroll
        for (int i = 0; i < 8; i++)
            wv[i] = reinterpret_cast<const float4*>(Ug + i * K)[tt];
    } else if (idx < 320) {
        // group A: front-batch V-slice batch 1
        ac = idx >> 5; aq = (idx >> 3) & 3; ads = idx & 7;
#pragma unroll
        for (int i = 0; i < 8; i++)
            av[i] = V4[(ads * 16 + i) * 128 + bx4 + aq];
    }
    __syncthreads();                        // #1: sx, smu ready

    if (t < 640) {
        // -------- group B: phase B straight through --------
        float4 acc = make_float4(0.f, 0.f, 0.f, 0.f);
        const float* sg = sx + g * 16;
#pragma unroll
        for (int i = 0; i < 8; i++) {
            const float sv = sg[i];
            acc.x = fmaf(sv, wv[i].x, acc.x);
            acc.y = fmaf(sv, wv[i].y, acc.y);
            acc.z = fmaf(sv, wv[i].z, acc.z);
            acc.w = fmaf(sv, wv[i].w, acc.w);
        }
#pragma unroll
        for (int i = 0; i < 8; i++)
            wv[i] = reinterpret_cast<const float4*>(Ug + (8 + i) * K)[tt];
#pragma unroll
        for (int i = 0; i < 8; i++) {
            const float sv = sg[8 + i];
            acc.x = fmaf(sv, wv[i].x, acc.x);
            acc.y = fmaf(sv, wv[i].y, acc.y);
            acc.z = fmaf(sv, wv[i].z, acc.z);
            acc.w = fmaf(sv, wv[i].w, acc.w);
        }
        reinterpret_cast<float4*>(&part[g][tt * 4])[0] = acc;
    } else {
        // -------- group A: fac2 k-slice, then late phase B --------
        if (idx < 320) {
            float4 acc = make_float4(0.f, 0.f, 0.f, 0.f);
            const float* muc = smu + ac * D + ads * 16;
#pragma unroll
            for (int i = 0; i < 8; i++) {
                const float sv = muc[i];
                acc.x = fmaf(sv, av[i].x, acc.x);
                acc.y = fmaf(sv, av[i].y, acc.y);
                acc.z = fmaf(sv, av[i].z, acc.z);
                acc.w = fmaf(sv, av[i].w, acc.w);
            }
#pragma unroll
            for (int i = 0; i < 8; i++)
                av[i] = V4[(ads * 16 + 8 + i) * 128 + bx4 + aq];
#pragma unroll
            for (int i = 0; i < 8; i++) {
                const float sv = muc[8 + i];
                acc.x = fmaf(sv, av[i].x, acc.x);
                acc.y = fmaf(sv, av[i].y, acc.y);
                acc.z = fmaf(sv, av[i].z, acc.z);
                acc.w = fmaf(sv, av[i].w, acc.w);
            }
            part2[ac][aq][ads] = acc;
        }
        bar_sync_grp(1, 384);               // group-A barrier (warps 20-31)
        if (idx < 40) {                     // reduce 8 d-splits, publish slice
            const int c = idx >> 2, q = idx & 3;
            float4 r = make_float4(0.f, 0.f, 0.f, 0.f);
#pragma unroll
            for (int ds = 0; ds < 8; ds++) {
                float4 a = part2[c][q][ds];
                r.x += a.x; r.y += a.y; r.z += a.z; r.w += a.w;
            }
            reinterpret_cast<float4*>(&g_fac2[c][0])[bx4 + q] = r;
        }
        bar_sync_grp(1, 384);               // slice stores drained
        if (idx == 0) st_release_gpu(&g_pflag[row], 1);

        // late phase B for d-groups 5..7 (hidden under the L1 wf queue)
        float4 acc = make_float4(0.f, 0.f, 0.f, 0.f);
        const float* sg = sx + g * 16;
#pragma unroll
        for (int i = 0; i < 8; i++)
            wv[i] = reinterpret_cast<const float4*>(Ug + i * K)[tt];
#pragma unroll
        for (int i = 0; i < 8; i++) {
            const float sv = sg[i];
            acc.x = fmaf(sv, wv[i].x, acc.x);
            acc.y = fmaf(sv, wv[i].y, acc.y);
            acc.z = fmaf(sv, wv[i].z, acc.z);
            acc.w = fmaf(sv, wv[i].w, acc.w);
        }
#pragma unroll
        for (int i = 0; i < 8; i++)
            wv[i] = reinterpret_cast<const float4*>(Ug + (8 + i) * K)[tt];
#pragma unroll
        for (int i = 0; i < 8; i++) {
            const float sv = sg[8 + i];
            acc.x = fmaf(sv, wv[i].x, acc.x);
            acc.y = fmaf(sv, wv[i].y, acc.y);
            acc.z = fmaf(sv, wv[i].z, acc.z);
            acc.w = fmaf(sv, wv[i].w, acc.w);
        }
        reinterpret_cast<float4*>(&part[g][tt * 4])[0] = acc;
    }
    __syncthreads();                        // #2: all part[] written

    // fold d-group partials while thread 0 polls the 32 flags
    if (t == 0) {
        const int4* fp = reinterpret_cast<const int4*>(g_pflag);
        for (;;) {
            int s = 0;
#pragma unroll
            for (int j = 0; j < NFLAG / 4; j++) {
                int4 f = ld_volatile_v4(fp + j);
                s += f.x + f.y + f.z + f.w;
            }
            if (s == NFLAG) break;
        }
        fence_acq_rel_gpu();
    }
    if (t >= 512) {                         // disjoint warps fold while warp 0 polls
        const int k = t - 512;
        float f = part[0][k];
#pragma unroll
        for (int gg = 1; gg < 8; gg++) f += part[gg][k];
        f1s[k] = f;
    }
    __syncthreads();                        // #3: f1s ready AND fac2 visible

    // one warp per class: dot(f1s, fac2[c]) over K=512 (4 float4 per lane)
    if (w < C) {
        const float4* fa = reinterpret_cast<const float4*>(f1s);
        const float4* fb = reinterpret_cast<const float4*>(&g_fac2[w][0]);
        float p = 0.f;
#pragma unroll
        for (int j = 0; j < 4; j++) {
            const int i4 = lane + j * 32;
            float4 a = fa[i4];
            float4 b2 = fb[i4];
            p += a.x * b2.x + a.y * b2.y + a.z * b2.z + a.w * b2.w;
        }
#pragma unroll
        for (int o = 16; o > 0; o >>= 1)
            p += __shfl_xor_sync(0xffffffffu, p, o);
        if (lane == 0) hrow[w] = p;
    }
    __syncthreads();                        // #4

    // parallel log_softmax in warp 0 (fast MUFU path)
    if (w == 0) {
        float h = (lane < C) ? hrow[lane] : -INFINITY;
        float m = h;
#pragma unroll
        for (int o = 8; o > 0; o >>= 1)
            m = fmaxf(m, __shfl_xor_sync(0xffffffffu, m, o));
        m = __shfl_sync(0xffffffffu, m, 0);
        float e = (lane < C) ? __expf(h - m) : 0.f;
        float se = e;
#pragma unroll
        for (int o = 8; o > 0; o >>= 1)
            se += __shfl_xor_sync(0xffffffffu, se, o);
        se = __shfl_sync(0xffffffffu, se, 0);
        const float lse = m + __logf(se);
        if (lane < C) out[row * C + lane] = h - lse;

        // last CTA resets flags for the next graph replay
        if (lane == 0 && atomicAdd(&g_done, 1) == B - 1) {
#pragma unroll
            for (int j = 0; j < NFLAG; j++) g_pflag[j] = 0;
            g_done = 0;
        }
    }
}

extern "C" void kernel_launch(void* const* d_in, const int* in_sizes, int n_in,
                              void* d_out, int out_size) {
    const float* x  = (const float*)d_in[0];  // [32, 128]
    const float* mu = (const float*)d_in[1];  // [10, 128]
    const float* U  = (const float*)d_in[2];  // [128, 512]
    const float* V  = (const float*)d_in[3];  // [128, 512]
    float* out = (float*)d_out;               // [32, 10]

    fused_kernel<<<B, NT>>>(x, mu, U, V, out);
}

// round 14
// speedup vs baseline: 1.1591x; 1.1591x over previous
#include <cuda_runtime.h>
#include <math.h>

// Problem constants (hardcoded in reference)
#define B 32
#define D 128
#define K 512
#define C 10
#define NT 1024

// Cross-CTA state
__device__ float g_fac2[C][K];
__device__ int g_pflag[C];    // per-producer release flags
__device__ int g_done = 0;    // consumers done (target B)

__device__ __forceinline__ void st_release_gpu(int* p, int v) {
    asm volatile("st.release.gpu.global.s32 [%0], %1;" :: "l"(p), "r"(v) : "memory");
}
__device__ __forceinline__ int ld_acquire_gpu(const int* p) {
    int v;
    asm volatile("ld.acquire.gpu.global.s32 %0, [%1];" : "=r"(v) : "l"(p) : "memory");
    return v;
}

// 42 CTAs x 1024 threads (one CTA per SM, single wave):
//   CTA 0..31  : consumer b — fac1 row in smem partials; each class-warp
//                polls its own flag (overlapped with the fold), dots, softmax.
//   CTA 32..41 : producer c — fac2 row, publish slice + release flag.
__global__ __launch_bounds__(NT, 1) void fused_kernel(
    const float* __restrict__ x,
    const float* __restrict__ mu,
    const float* __restrict__ U,
    const float* __restrict__ V,
    float* __restrict__ out) {
    __shared__ float sx[D];
    __shared__ float part[8][K];     // 8 d-groups x 512 (16 KB)
    __shared__ float f1s[K];
    __shared__ float hrow[C];

    const int t    = threadIdx.x;
    const int w    = t >> 5;
    const int lane = t & 31;
    const int g    = t >> 7;         // d-group 0..7 (16 d-rows each)
    const int tt   = t & 127;        // float4 col, full K

    const bool producer = (blockIdx.x >= B);
    const int  row = producer ? (blockIdx.x - B) : blockIdx.x;
    const float* src = producer ? (mu + row * D) : (x + row * D);
    const float* Wg  = (producer ? V : U) + g * 16 * K;

    if (t < D) sx[t] = src[t];

    // front-batched: all 16 LDG.128 in flight before the smem-operand wait
    float4 wv[16];
#pragma unroll
    for (int i = 0; i < 16; i++)
        wv[i] = reinterpret_cast<const float4*>(Wg + i * K)[tt];
    __syncthreads();

    float4 acc = make_float4(0.f, 0.f, 0.f, 0.f);
    const float* sg = sx + g * 16;
#pragma unroll
    for (int i = 0; i < 16; i++) {
        const float sv = sg[i];
        acc.x = fmaf(sv, wv[i].x, acc.x);
        acc.y = fmaf(sv, wv[i].y, acc.y);
        acc.z = fmaf(sv, wv[i].z, acc.z);
        acc.w = fmaf(sv, wv[i].w, acc.w);
    }
    reinterpret_cast<float4*>(&part[g][tt * 4])[0] = acc;
    __syncthreads();

    if (producer) {
        // reduce 8 d-partials, publish fac2 row, release own flag
        if (t < 128) {
            float4 r = make_float4(0.f, 0.f, 0.f, 0.f);
#pragma unroll
            for (int gg = 0; gg < 8; gg++) {
                float4 a = reinterpret_cast<const float4*>(&part[gg][t * 4])[0];
                r.x += a.x; r.y += a.y; r.z += a.z; r.w += a.w;
            }
            reinterpret_cast<float4*>(&g_fac2[row][0])[t] = r;
        }
        __syncthreads();                 // row stores happen-before flag
        if (t == 0) st_release_gpu(&g_pflag[row], 1);
        return;
    }

    // ---------------- consumer ----------------
    // warps 16..31 fold d-group partials WHILE warps 0..9 poll their own flag
    if (t >= 512) {
        const int k = t - 512;
        float f = part[0][k];
#pragma unroll
        for (int gg = 1; gg < 8; gg++) f += part[gg][k];
        f1s[k] = f;
    } else if (w < C) {
        // per-lane acquire poll on this class's flag (broadcast load)
        while (ld_acquire_gpu(&g_pflag[w]) == 0) { }
    }
    __syncthreads();                     // f1s ready; fac2[w] acquired per-lane

    // one warp per class: dot(f1s, fac2[c]) over K=512 (4 float4 per lane)
    if (w < C) {
        const float4* fa = reinterpret_cast<const float4*>(f1s);
        const float4* fb = reinterpret_cast<const float4*>(&g_fac2[w][0]);
        float p = 0.f;
#pragma unroll
        for (int j = 0; j < 4; j++) {
            const int i4 = lane + j * 32;
            float4 a = fa[i4];
            float4 b2 = fb[i4];
            p += a.x * b2.x + a.y * b2.y + a.z * b2.z + a.w * b2.w;
        }
#pragma unroll
        for (int o = 16; o > 0; o >>= 1)
            p += __shfl_xor_sync(0xffffffffu, p, o);
        if (lane == 0) hrow[w] = p;
    }
    __syncthreads();

    // parallel log_softmax in warp 0: lane c owns class c (fast MUFU path)
    if (w == 0) {
        float h = (lane < C) ? hrow[lane] : -INFINITY;
        float m = h;
#pragma unroll
        for (int o = 8; o > 0; o >>= 1)
            m = fmaxf(m, __shfl_xor_sync(0xffffffffu, m, o));
        m = __shfl_sync(0xffffffffu, m, 0);
        float e = (lane < C) ? __expf(h - m) : 0.f;   // MUFU.EX2
        float se = e;
#pragma unroll
        for (int o = 8; o > 0; o >>= 1)
            se += __shfl_xor_sync(0xffffffffu, se, o);
        se = __shfl_sync(0xffffffffu, se, 0);
        const float lse = m + __logf(se);             // MUFU.LG2
        if (lane < C) out[row * C + lane] = h - lse;

        // last consumer resets flags (parallel across lanes) for next replay
        int last = 0;
        if (lane == 0) last = (atomicAdd(&g_done, 1) == B - 1);
        last = __shfl_sync(0xffffffffu, last, 0);
        if (last) {
            if (lane < C) g_pflag[lane] = 0;
            if (lane == C) g_done = 0;
        }
    }
}

extern "C" void kernel_launch(void* const* d_in, const int* in_sizes, int n_in,
                              void* d_out, int out_size) {
    const float* x  = (const float*)d_in[0];  // [32, 128]
    const float* mu = (const float*)d_in[1];  // [10, 128]
    const float* U  = (const float*)d_in[2];  // [128, 512]
    const float* V  = (const float*)d_in[3];  // [128, 512]
    float* out = (float*)d_out;               // [32, 10]

    fused_kernel<<<B + C, NT>>>(x, mu, U, V, out);
}

// round 15
// speedup vs baseline: 1.1895x; 1.0262x over previous
#include <cuda_runtime.h>
#include <math.h>

// Problem constants (hardcoded in reference)
#define B 32
#define D 128
#define K 512
#define C 10
#define NT 1024

// Cross-CTA state
__device__ float g_fac2[C][K];
__device__ int g_pflag[C];    // per-producer release flags
__device__ int g_done = 0;    // consumers done (target B)

__device__ __forceinline__ void st_release_gpu(int* p, int v) {
    asm volatile("st.release.gpu.global.s32 [%0], %1;" :: "l"(p), "r"(v) : "memory");
}
__device__ __forceinline__ int ld_acquire_gpu(const int* p) {
    int v;
    asm volatile("ld.acquire.gpu.global.s32 %0, [%1];" : "=r"(v) : "l"(p) : "memory");
    return v;
}

// 42 CTAs x 1024 threads (one CTA per SM, single wave):
//   CTA 0..31  : consumer b — fac1 row in smem partials; dot-warp lane0 polls
//                its own flag, warp prefetches fac2 into regs UNDER the fold,
//                then LDS+FMA dot, parallel fast softmax.
//   CTA 32..41 : producer c — fac2 row, publish slice + release flag.
__global__ __launch_bounds__(NT, 1) void fused_kernel(
    const float* __restrict__ x,
    const float* __restrict__ mu,
    const float* __restrict__ U,
    const float* __restrict__ V,
    float* __restrict__ out) {
    __shared__ float sx[D];
    __shared__ float part[8][K];     // 8 d-groups x 512 (16 KB)
    __shared__ float f1s[K];
    __shared__ float hrow[C];

    const int t    = threadIdx.x;
    const int w    = t >> 5;
    const int lane = t & 31;
    const int g    = t >> 7;         // d-group 0..7 (16 d-rows each)
    const int tt   = t & 127;        // float4 col, full K

    const bool producer = (blockIdx.x >= B);
    const int  row = producer ? (blockIdx.x - B) : blockIdx.x;
    const float* src = producer ? (mu + row * D) : (x + row * D);
    const float* Wg  = (producer ? V : U) + g * 16 * K;

    if (t < D) sx[t] = src[t];

    // front-batched: all 16 LDG.128 in flight before the smem-operand wait
    float4 wv[16];
#pragma unroll
    for (int i = 0; i < 16; i++)
        wv[i] = reinterpret_cast<const float4*>(Wg + i * K)[tt];
    __syncthreads();

    float4 acc = make_float4(0.f, 0.f, 0.f, 0.f);
    const float* sg = sx + g * 16;
#pragma unroll
    for (int i = 0; i < 16; i++) {
        const float sv = sg[i];
        acc.x = fmaf(sv, wv[i].x, acc.x);
        acc.y = fmaf(sv, wv[i].y, acc.y);
        acc.z = fmaf(sv, wv[i].z, acc.z);
        acc.w = fmaf(sv, wv[i].w, acc.w);
    }
    reinterpret_cast<float4*>(&part[g][tt * 4])[0] = acc;
    __syncthreads();

    if (producer) {
        // reduce 8 d-partials, publish fac2 row, release own flag
        if (t < 128) {
            float4 r = make_float4(0.f, 0.f, 0.f, 0.f);
#pragma unroll
            for (int gg = 0; gg < 8; gg++) {
                float4 a = reinterpret_cast<const float4*>(&part[gg][t * 4])[0];
                r.x += a.x; r.y += a.y; r.z += a.z; r.w += a.w;
            }
            reinterpret_cast<float4*>(&g_fac2[row][0])[t] = r;
        }
        __syncthreads();                 // row stores happen-before flag
        if (t == 0) st_release_gpu(&g_pflag[row], 1);
        return;
    }

    // ---------------- consumer ----------------
    // warps 16..31 fold d-group partials WHILE each dot warp (0..9) polls its
    // own flag (lane 0 only: 10 polling threads) and prefetches fac2 to regs.
    float4 fb[4];
    if (t >= 512) {
        const int k = t - 512;
        float f = part[0][k];
#pragma unroll
        for (int gg = 1; gg < 8; gg++) f += part[gg][k];
        f1s[k] = f;
    } else if (w < C) {
        if (lane == 0) {
            while (ld_acquire_gpu(&g_pflag[w]) == 0) { }
        }
        __syncwarp();                    // extends lane0's acquire to the warp
        const float4* fbp = reinterpret_cast<const float4*>(&g_fac2[w][0]);
#pragma unroll
        for (int j = 0; j < 4; j++)
            fb[j] = fbp[lane + j * 32];  // L2 latency hidden under the fold
    }
    __syncthreads();                     // f1s ready; fb in regs

    // one warp per class: dot(f1s, fb) — pure LDS + FMA now
    if (w < C) {
        const float4* fa = reinterpret_cast<const float4*>(f1s);
        float p = 0.f;
#pragma unroll
        for (int j = 0; j < 4; j++) {
            float4 a = fa[lane + j * 32];
            p += a.x * fb[j].x + a.y * fb[j].y + a.z * fb[j].z + a.w * fb[j].w;
        }
#pragma unroll
        for (int o = 16; o > 0; o >>= 1)
            p += __shfl_xor_sync(0xffffffffu, p, o);
        if (lane == 0) hrow[w] = p;
    }
    __syncthreads();

    // parallel log_softmax in warp 0: lane c owns class c (fast MUFU path)
    if (w == 0) {
        float h = (lane < C) ? hrow[lane] : -INFINITY;
        float m = h;
#pragma unroll
        for (int o = 8; o > 0; o >>= 1)
            m = fmaxf(m, __shfl_xor_sync(0xffffffffu, m, o));
        m = __shfl_sync(0xffffffffu, m, 0);
        float e = (lane < C) ? __expf(h - m) : 0.f;   // MUFU.EX2
        float se = e;
#pragma unroll
        for (int o = 8; o > 0; o >>= 1)
            se += __shfl_xor_sync(0xffffffffu, se, o);
        se = __shfl_sync(0xffffffffu, se, 0);
        const float lse = m + __logf(se);             // MUFU.LG2
        if (lane < C) out[row * C + lane] = h - lse;

        // last consumer resets flags (parallel across lanes) for next replay
        int last = 0;
        if (lane == 0) last = (atomicAdd(&g_done, 1) == B - 1);
        last = __shfl_sync(0xffffffffu, last, 0);
        if (last) {
            if (lane < C) g_pflag[lane] = 0;
            if (lane == C) g_done = 0;
        }
    }
}

extern "C" void kernel_launch(void* const* d_in, const int* in_sizes, int n_in,
                              void* d_out, int out_size) {
    const float* x  = (const float*)d_in[0];  // [32, 128]
    const float* mu = (const float*)d_in[1];  // [10, 128]
    const float* U  = (const float*)d_in[2];  // [128, 512]
    const float* V  = (const float*)d_in[3];  // [128, 512]
    float* out = (float*)d_out;               // [32, 10]

    fused_kernel<<<B + C, NT>>>(x, mu, U, V, out);
}